// round 17
// baseline (speedup 1.0000x reference)
#include <cuda_runtime.h>

#define BATCH   262144
#define T_STEPS 20
#define BETAF   0.9f
#define THRESHF 1.0f

using u32 = unsigned int;
using u64 = unsigned long long;

__device__ __forceinline__ u64 pack2(float lo, float hi) {
    u64 r; asm("mov.b64 %0, {%1, %2};" : "=l"(r) : "f"(lo), "f"(hi)); return r;
}
__device__ __forceinline__ void unpack2(u64 v, float &lo, float &hi) {
    asm("mov.b64 {%0, %1}, %2;" : "=f"(lo), "=f"(hi) : "l"(v));
}
__device__ __forceinline__ u64 packi(u32 lo, u32 hi) {
    u64 r; asm("mov.b64 %0, {%1, %2};" : "=l"(r) : "r"(lo), "r"(hi)); return r;
}
__device__ __forceinline__ void unpacki(u64 v, u32 &lo, u32 &hi) {
    asm("mov.b64 {%0, %1}, %2;" : "=r"(lo), "=r"(hi) : "l"(v));
}
// Packed dual fp32 FMA (2 MACs / instruction on the fma pipe)
__device__ __forceinline__ u64 ffma2(u64 a, u64 b, u64 c) {
    u64 d; asm("fma.rn.f32x2 %0, %1, %2, %3;" : "=l"(d) : "l"(a), "l"(b), "l"(c)); return d;
}

#define ONE2 0x3F8000003F800000ull

// ---- static smem weights, quarter-contiguous (warp-uniform addressing) ----
__shared__ u64 sW1[4 * 10 * 8];  // 10 -> 64, P4=8
__shared__ u64 sW2[4 * 64 * 4];  // 64 -> 32, P4=4
__shared__ u64 sW3[4 * 32 * 4];  // 32 -> 32, P4=4
__shared__ u64 sW4[4 * 32 * 2];  // 32 -> 16, P4=2
__shared__ u64 sW5[4 * 16 * 1];  // 16 -> 6 (padded to 8), P4=1
// spike-mask exchange: [region][wq][lane][el0,el1] (u32 units; u64 accesses)
__shared__ u32 spk[4 * 4 * 32 * 2];

__device__ __forceinline__ void stage(u64* dst, const float* __restrict__ W,
                                      int NIN, int NOUT, int P4, int tid) {
    int total = 4 * NIN * P4;
    for (int idx = tid; idx < total; idx += 128) {
        int q = idx / (NIN * P4);
        int r = idx % (NIN * P4);
        int i = r / P4, p = r % P4;
        int j0 = q * (2 * P4) + 2 * p;
        float a = (j0     < NOUT) ? W[j0 * NIN + i]       : 0.0f;
        float b = (j0 + 1 < NOUT) ? W[(j0 + 1) * NIN + i] : 0.0f;
        dst[idx] = pack2(a, b);
    }
}

// LIF for one output pair; returns 2-bit spike mask. Same formula/order as rounds 1-16.
__device__ __forceinline__ u32 lif_pair(u64 acc, float &mA, float &mB) {
    float a0, a1; unpack2(acc, a0, a1);
    float r0 = mA > THRESHF ? THRESHF : 0.0f;
    float r1 = mB > THRESHF ? THRESHF : 0.0f;
    mA = fmaf(BETAF, mA, a0 - r0);
    mB = fmaf(BETAF, mB, a1 - r1);
    u32 m = 0;
    if (mA > THRESHF) m |= 1u;
    if (mB > THRESHF) m |= 2u;
    return m;
}

// OR of the 4 quarter-words of one exchange region for this lane.
__device__ __forceinline__ u64 read_region(const u32* sp, int lane) {
    return (*(const u64*)(sp + 0 * 64 + lane * 2))
         | (*(const u64*)(sp + 1 * 64 + lane * 2))
         | (*(const u64*)(sp + 2 * 64 + lane * 2))
         | (*(const u64*)(sp + 3 * 64 + lane * 2));
}

// Layer-1 compute for step ts (identical arithmetic/order to rounds 11-16).
__device__ __forceinline__ void l1_step(
    const float* __restrict__ x, int ts, size_t eglob,
    const u64* __restrict__ w1, float (&m1)[2][16],
    u32* sp1, int myoff, int wq)
{
    float2 xv[2][5];
#pragma unroll
    for (int el = 0; el < 2; ++el) {
        const float2* xp = (const float2*)(x + ((size_t)ts * BATCH + eglob + el) * 10);
#pragma unroll
        for (int i = 0; i < 5; ++i) xv[el][i] = xp[i];
    }
    u64 acc1[2][8];
#pragma unroll
    for (int el = 0; el < 2; ++el)
#pragma unroll
        for (int p = 0; p < 8; ++p) acc1[el][p] = 0ull;
#pragma unroll
    for (int i = 0; i < 10; ++i) {
        const ulonglong2* wp = (const ulonglong2*)(w1 + i * 8);
        ulonglong2 wa = wp[0], wb = wp[1], wc = wp[2], wd = wp[3];
#pragma unroll
        for (int el = 0; el < 2; ++el) {
            float xf = (i & 1) ? xv[el][i >> 1].y : xv[el][i >> 1].x;
            u64 xd = pack2(xf, xf);
            acc1[el][0] = ffma2(xd, wa.x, acc1[el][0]);
            acc1[el][1] = ffma2(xd, wa.y, acc1[el][1]);
            acc1[el][2] = ffma2(xd, wb.x, acc1[el][2]);
            acc1[el][3] = ffma2(xd, wb.y, acc1[el][3]);
            acc1[el][4] = ffma2(xd, wc.x, acc1[el][4]);
            acc1[el][5] = ffma2(xd, wc.y, acc1[el][5]);
            acc1[el][6] = ffma2(xd, wd.x, acc1[el][6]);
            acc1[el][7] = ffma2(xd, wd.y, acc1[el][7]);
        }
    }
    u32 m16[2];
#pragma unroll
    for (int el = 0; el < 2; ++el) {
        u32 mk = 0;
#pragma unroll
        for (int p = 0; p < 8; ++p)
            mk |= lif_pair(acc1[el][p], m1[el][2 * p], m1[el][2 * p + 1]) << (2 * p);
        m16[el] = mk;
    }
    u32 s0 = (wq & 1) ? (m16[0] << 16) : m16[0];
    u32 s1 = (wq & 1) ? (m16[1] << 16) : m16[1];
    *(u64*)(sp1 + myoff) = packi(s0, s1);
    // prefetch the step AFTER ts into L2 (80 contiguous bytes)
    {
        size_t tn = (ts + 1 < T_STEPS) ? (size_t)(ts + 1) : (size_t)ts;
        const char* nx = (const char*)(x + (tn * BATCH + eglob) * 10);
        asm volatile("prefetch.global.L2 [%0];" :: "l"(nx));
        asm volatile("prefetch.global.L2 [%0];" :: "l"(nx + 79));
    }
}

// Layer-2 compute: consumes L1 masks (lo/hi per element), updates m2, STS to sp2.
__device__ __forceinline__ void l2_step(
    const u32 lo[2], const u32 hi[2],
    const u64* __restrict__ w2, float (&m2)[2][8],
    u32* sp2, int myoff, int wq)
{
    u64 acc2[2][4];
#pragma unroll
    for (int el = 0; el < 2; ++el)
#pragma unroll
        for (int p = 0; p < 4; ++p) acc2[el][p] = 0ull;
#pragma unroll
    for (int i = 0; i < 64; ++i) {
        const ulonglong2* wp = (const ulonglong2*)(w2 + i * 4);
        ulonglong2 wa = wp[0], wb = wp[1];
        u32 bit = 1u << (i & 31);
        u64 h0 = (((i < 32) ? lo[0] : hi[0]) & bit) ? ONE2 : 0ull;
        u64 h1 = (((i < 32) ? lo[1] : hi[1]) & bit) ? ONE2 : 0ull;
        acc2[0][0] = ffma2(h0, wa.x, acc2[0][0]);
        acc2[0][1] = ffma2(h0, wa.y, acc2[0][1]);
        acc2[0][2] = ffma2(h0, wb.x, acc2[0][2]);
        acc2[0][3] = ffma2(h0, wb.y, acc2[0][3]);
        acc2[1][0] = ffma2(h1, wa.x, acc2[1][0]);
        acc2[1][1] = ffma2(h1, wa.y, acc2[1][1]);
        acc2[1][2] = ffma2(h1, wb.x, acc2[1][2]);
        acc2[1][3] = ffma2(h1, wb.y, acc2[1][3]);
    }
    u32 a0 = 0, a1 = 0;
#pragma unroll
    for (int p = 0; p < 4; ++p) {
        a0 |= lif_pair(acc2[0][p], m2[0][2 * p], m2[0][2 * p + 1]) << (2 * p);
        a1 |= lif_pair(acc2[1][p], m2[1][2 * p], m2[1][2 * p + 1]) << (2 * p);
    }
    *(u64*)(sp2 + myoff) = packi(a0 << (wq * 8), a1 << (wq * 8));
}

__global__ __launch_bounds__(128, 3) void lif_kernel(
    const float* __restrict__ x,
    const float* __restrict__ W1, const float* __restrict__ W2,
    const float* __restrict__ W3, const float* __restrict__ W4,
    const float* __restrict__ W5, float* __restrict__ out)
{
    const int tid = threadIdx.x;
    stage(sW1, W1, 10, 64, 8, tid);
    stage(sW2, W2, 64, 32, 4, tid);
    stage(sW3, W3, 32, 32, 4, tid);
    stage(sW4, W4, 32, 16, 2, tid);
    stage(sW5, W5, 16,  6, 1, tid);

    const int wq   = tid >> 5;      // warp = quarter of every layer's outputs
    const int lane = tid & 31;
    const size_t eglob = (size_t)blockIdx.x * 64 + lane * 2;  // elements 2*lane, 2*lane+1

    const u64* w1 = sW1 + wq * (10 * 8);
    const u64* w2 = sW2 + wq * (64 * 4);
    const u64* w3 = sW3 + wq * (32 * 4);
    const u64* w4 = sW4 + wq * (32 * 2);
    const u64* w5 = sW5 + wq * 16;
    u32* sp1 = spk;           // each region: [4 wq][32 lane][2 el]
    u32* sp2 = spk + 256;
    u32* sp3 = spk + 512;
    u32* sp4 = spk + 768;
    const int myoff = wq * 64 + lane * 2;

    // membrane state: quarter of every layer, E=2 elements (38 floats each)
    float m1[2][16], m2[2][8], m3[2][8], m4[2][4], m5[2][2];
#pragma unroll
    for (int el = 0; el < 2; ++el) {
#pragma unroll
        for (int k = 0; k < 16; ++k) m1[el][k] = 0.f;
#pragma unroll
        for (int k = 0; k < 8; ++k) { m2[el][k] = 0.f; m3[el][k] = 0.f; }
#pragma unroll
        for (int k = 0; k < 4; ++k)  m4[el][k] = 0.f;
#pragma unroll
        for (int k = 0; k < 2; ++k)  m5[el][k] = 0.f;
    }

    __syncthreads();              // weights staged

    // ---- prologue: L1(0); exchange; L2(0); L1(1); exchange ----
    l1_step(x, 0, eglob, w1, m1, sp1, myoff, wq);
    __syncthreads();
    u32 lo[2], hi[2];
    { u64 v0, v1;
      v0 = (*(const u64*)(sp1 + 0 * 64 + lane * 2)) | (*(const u64*)(sp1 + 1 * 64 + lane * 2));
      v1 = (*(const u64*)(sp1 + 2 * 64 + lane * 2)) | (*(const u64*)(sp1 + 3 * 64 + lane * 2));
      unpacki(v0, lo[0], lo[1]); unpacki(v1, hi[0], hi[1]); }
    __syncthreads();              // all sp1(0) reads done before sp1(1) write below
    l2_step(lo, hi, w2, m2, sp2, myoff, wq);     // L2(0) -> sp2
    l1_step(x, 1, eglob, w1, m1, sp1, myoff, wq);// L1(1) -> sp1
    __syncthreads();
    u32 f2[2];
    { u64 v = read_region(sp2, lane); unpacki(v, f2[0], f2[1]); }    // f2(0)
    { u64 v0, v1;
      v0 = (*(const u64*)(sp1 + 0 * 64 + lane * 2)) | (*(const u64*)(sp1 + 1 * 64 + lane * 2));
      v1 = (*(const u64*)(sp1 + 2 * 64 + lane * 2)) | (*(const u64*)(sp1 + 3 * 64 + lane * 2));
      unpacki(v0, lo[0], lo[1]); unpacki(v1, hi[0], hi[1]); }        // L1 masks(1)

#pragma unroll 1
    for (int t = 0; t < T_STEPS; ++t) {
        // ================= Layer 3 (t): 32 -> 32 =================
        u64 acc3[2][4];
#pragma unroll
        for (int el = 0; el < 2; ++el)
#pragma unroll
            for (int p = 0; p < 4; ++p) acc3[el][p] = 0ull;
#pragma unroll
        for (int i = 0; i < 32; ++i) {
            const ulonglong2* wp = (const ulonglong2*)(w3 + i * 4);
            ulonglong2 wa = wp[0], wb = wp[1];
            u32 bit = 1u << i;
            u64 h0 = (f2[0] & bit) ? ONE2 : 0ull;
            u64 h1 = (f2[1] & bit) ? ONE2 : 0ull;
            acc3[0][0] = ffma2(h0, wa.x, acc3[0][0]);
            acc3[0][1] = ffma2(h0, wa.y, acc3[0][1]);
            acc3[0][2] = ffma2(h0, wb.x, acc3[0][2]);
            acc3[0][3] = ffma2(h0, wb.y, acc3[0][3]);
            acc3[1][0] = ffma2(h1, wa.x, acc3[1][0]);
            acc3[1][1] = ffma2(h1, wa.y, acc3[1][1]);
            acc3[1][2] = ffma2(h1, wb.x, acc3[1][2]);
            acc3[1][3] = ffma2(h1, wb.y, acc3[1][3]);
        }
        {
            u32 a0 = 0, a1 = 0;
#pragma unroll
            for (int p = 0; p < 4; ++p) {
                a0 |= lif_pair(acc3[0][p], m3[0][2 * p], m3[0][2 * p + 1]) << (2 * p);
                a1 |= lif_pair(acc3[1][p], m3[1][2 * p], m3[1][2 * p + 1]) << (2 * p);
            }
            *(u64*)(sp3 + myoff) = packi(a0 << (wq * 8), a1 << (wq * 8));
        }
        __syncthreads();                         // barrier A: releases sp3(t)
        u32 f3[2];
        { u64 v = read_region(sp3, lane); unpacki(v, f3[0], f3[1]); }

        // ================= Layer 4 (t): 32 -> 16 =================
        u64 acc4[2][2];
#pragma unroll
        for (int el = 0; el < 2; ++el) { acc4[el][0] = 0ull; acc4[el][1] = 0ull; }
#pragma unroll
        for (int i = 0; i < 32; ++i) {
            const ulonglong2* wp = (const ulonglong2*)(w4 + i * 2);
            ulonglong2 wa = wp[0];
            u32 bit = 1u << i;
            u64 h0 = (f3[0] & bit) ? ONE2 : 0ull;
            u64 h1 = (f3[1] & bit) ? ONE2 : 0ull;
            acc4[0][0] = ffma2(h0, wa.x, acc4[0][0]);
            acc4[0][1] = ffma2(h0, wa.y, acc4[0][1]);
            acc4[1][0] = ffma2(h1, wa.x, acc4[1][0]);
            acc4[1][1] = ffma2(h1, wa.y, acc4[1][1]);
        }
        {
            u32 a0 = lif_pair(acc4[0][0], m4[0][0], m4[0][1])
                   | (lif_pair(acc4[0][1], m4[0][2], m4[0][3]) << 2);
            u32 a1 = lif_pair(acc4[1][0], m4[1][0], m4[1][1])
                   | (lif_pair(acc4[1][1], m4[1][2], m4[1][3]) << 2);
            *(u64*)(sp4 + myoff) = packi(a0 << (wq * 4), a1 << (wq * 4));
        }

        // ---- pipelined: L2(t+1) and L1(t+2) fill the barrier-B shadow ----
        if (t + 1 < T_STEPS)
            l2_step(lo, hi, w2, m2, sp2, myoff, wq);
        if (t + 2 < T_STEPS)
            l1_step(x, t + 2, eglob, w1, m1, sp1, myoff, wq);

        __syncthreads();          // barrier B: releases sp4(t), sp2(t+1), sp1(t+2)

        u32 f4[2];
        { u64 v = read_region(sp4, lane); unpacki(v, f4[0], f4[1]); }

        // ================= Layer 5 (t): 16 -> 6 =================
        u64 acc5[2];
        acc5[0] = 0ull; acc5[1] = 0ull;
#pragma unroll
        for (int i = 0; i < 16; ++i) {
            u64 w = w5[i];
            u32 bit = 1u << i;
            u64 h0 = (f4[0] & bit) ? ONE2 : 0ull;
            u64 h1 = (f4[1] & bit) ? ONE2 : 0ull;
            acc5[0] = ffma2(h0, w, acc5[0]);
            acc5[1] = ffma2(h1, w, acc5[1]);
        }
#pragma unroll
        for (int el = 0; el < 2; ++el) {
            float a0, a1; unpack2(acc5[el], a0, a1);
            float r0 = m5[el][0] > THRESHF ? THRESHF : 0.0f;
            float r1 = m5[el][1] > THRESHF ? THRESHF : 0.0f;
            float mm0 = fmaf(BETAF, m5[el][0], a0 - r0);
            float mm1 = fmaf(BETAF, m5[el][1], a1 - r1);
            m5[el][0] = mm0; m5[el][1] = mm1;
            if (wq < 3) {
                float2 o;
                o.x = mm0 > THRESHF ? 1.0f : 0.0f;
                o.y = mm1 > THRESHF ? 1.0f : 0.0f;
                *(float2*)(out + ((size_t)t * BATCH + eglob + el) * 6 + wq * 2) = o;
            }
        }

        // ---- fetch next iteration's inputs (written before barrier B) ----
        if (t + 1 < T_STEPS) {
            u64 v = read_region(sp2, lane); unpacki(v, f2[0], f2[1]);   // f2(t+1)
        }
        if (t + 2 < T_STEPS) {
            u64 v0 = (*(const u64*)(sp1 + 0 * 64 + lane * 2))
                   | (*(const u64*)(sp1 + 1 * 64 + lane * 2));
            u64 v1 = (*(const u64*)(sp1 + 2 * 64 + lane * 2))
                   | (*(const u64*)(sp1 + 3 * 64 + lane * 2));
            unpacki(v0, lo[0], lo[1]); unpacki(v1, hi[0], hi[1]);       // masks(t+2)
        }
    }
}

extern "C" void kernel_launch(void* const* d_in, const int* in_sizes, int n_in,
                              void* d_out, int out_size) {
    const float *x = nullptr, *W1 = nullptr, *W2 = nullptr, *W3 = nullptr,
                *W4 = nullptr, *W5 = nullptr;
    for (int i = 0; i < n_in; ++i) {
        const float* p = (const float*)d_in[i];
        switch (in_sizes[i]) {
            case 52428800: x  = p; break;  // (20, 262144, 10)
            case 640:      W1 = p; break;  // (64, 10)
            case 2048:     W2 = p; break;  // (32, 64)
            case 1024:     W3 = p; break;  // (32, 32)
            case 512:      W4 = p; break;  // (16, 32)
            case 96:       W5 = p; break;  // (6, 16)
            default: break;
        }
    }
    float* out = (float*)d_out;
    // 4 warps per block = 4 output-quarters; 32 lanes x E=2 -> 64 elements per block
    lif_kernel<<<BATCH / 64, 128>>>(x, W1, W2, W3, W4, W5, out);
}